// round 17
// baseline (speedup 1.0000x reference)
#include <cuda_runtime.h>

// YOLO loss — 2-kernel pipeline; one thread per (cell, box) for 2x warps.
// Shuffle kept warp-converged (R16 deadlock fix).
// predictions: (B<=4096, 7, 7, 2, 85) fp32
// targets_boxes: (B, 20, 4) fp32 ; targets_labels: (B, 20) int32
// out: scalar fp32
//
// g_win encoding: 0 = no object (zero-initialized at module load, and
// restored to 0 by k_cell after each use). Otherwise value v in [1,20]
// means winner box index w = NBOX - v (atomicMax of NBOX-n == min n).

#define S_GRID 7
#define NB 2
#define NC 80
#define NBOX 20
#define CELLS (S_GRID * S_GRID)
#define ROW 85
#define THREADS 256
#define NWARPS (THREADS / 32)
#define FULLMASK 0xffffffffu
#define MAX_B 4096

__device__ int g_win[MAX_B * CELLS];   // 0 = none; else NBOX - box_index

// ---------------- encode: one thread per (image, box); also zeroes out ----
__global__ __launch_bounds__(THREADS)
void k_encode(const float* __restrict__ boxes, float* out, int total_tb)
{
    int i = blockIdx.x * THREADS + threadIdx.x;
    if (i == 0) *out = 0.0f;
    if (i >= total_tb) return;
    const int b = i / NBOX;
    const int n = i - b * NBOX;
    const float4 bb = *reinterpret_cast<const float4*>(boxes + (size_t)i * 4);
    float x = (bb.x + bb.z) * 0.5f;
    float y = (bb.y + bb.w) * 0.5f;
    int jb = min(max((int)floorf(x * (float)S_GRID), 0), S_GRID - 1);
    int ib = min(max((int)floorf(y * (float)S_GRID), 0), S_GRID - 1);
    atomicMax(&g_win[b * CELLS + ib * S_GRID + jb], NBOX - n);
}

// ---------------- one thread per (cell, box) ----------------
__global__ __launch_bounds__(THREADS)
void k_cell(const float* __restrict__ pred,
            const float* __restrict__ boxes,
            const int*   __restrict__ labels,
            float* __restrict__ out,
            int total_pairs, float inv_B)
{
    const int tid  = threadIdx.x;
    const int lane = tid & 31;
    const int wib  = tid >> 5;
    const int gi   = blockIdx.x * THREADS + tid;
    const int cg   = gi >> 1;        // cell index
    const int bx   = gi & 1;         // box index within cell

    float acc = 0.0f;
    bool  isobj = false;             // set only on the responsible lane
    int   offset = 0, lbl = 0;

    const bool inrange = (gi < total_pairs);

    // ---- phase 1 (converged at warp level for the shuffle) ----
    int   v = 0;
    float p[5] = {0, 0, 0, 0, 0};
    float tx = 0.f, ty = 0.f, tw = 0.f, th = 0.f;
    float iou = 0.0f;
    int   w = 0, bimg = 0;

    if (inrange) {
        v = g_win[cg];
        const float* r = pred + (size_t)cg * (NB * ROW) + bx * ROW;
        #pragma unroll
        for (int k = 0; k < 5; k++) p[k] = __ldcs(r + k);

        if (v != 0) {
            if (bx == 0) g_win[cg] = 0;           // restore zeroed invariant
            w    = NBOX - v;                      // winner box index
            bimg = cg / CELLS;
            const int cidx = cg - bimg * CELLS;
            const int ci   = cidx / S_GRID;
            const int cj   = cidx - ci * S_GRID;

            const float4 bb = *reinterpret_cast<const float4*>(
                boxes + ((size_t)bimg * NBOX + w) * 4);
            const float x = (bb.x + bb.z) * 0.5f;
            const float y = (bb.y + bb.w) * 0.5f;
            tw = bb.z - bb.x;
            th = bb.w - bb.y;
            tx = x * (float)S_GRID - (float)cj;
            ty = y * (float)S_GRID - (float)ci;

            // my box's IoU (exact reference op order)
            const float bx1 = tx - tw * 0.5f, by1 = ty - th * 0.5f;
            const float bx2 = tx + tw * 0.5f, by2 = ty + th * 0.5f;
            float ax1 = p[0] - p[2] * 0.5f, ay1 = p[1] - p[3] * 0.5f;
            float ax2 = p[0] + p[2] * 0.5f, ay2 = p[1] + p[3] * 0.5f;
            float iw = fmaxf(fminf(ax2, bx2) - fmaxf(ax1, bx1), 0.0f);
            float ih = fmaxf(fminf(ay2, by2) - fmaxf(ay1, by1), 0.0f);
            float inter = iw * ih;
            float uni = (ax2 - ax1) * (ay2 - ay1)
                      + (bx2 - bx1) * (by2 - by1) - inter;
            iou = inter / (uni + 1e-6f);
        }
    }

    // ---- pair exchange: executed by ALL lanes (warp converged) ----
    const float iou_o = __shfl_xor_sync(FULLMASK, iou, 1);

    // ---- phase 2: diverge for accumulation ----
    if (inrange) {
        if (v == 0) {
            acc = 0.5f * p[4] * p[4];             // LAMBDA_NOOBJ
        } else {
            const float iou0 = bx ? iou_o : iou;
            const float iou1 = bx ? iou : iou_o;
            const int best = (iou1 > iou0) ? 1 : 0;   // first max wins

            if (bx == best) {
                float dx = p[0] - tx, dy = p[1] - ty;
                acc += 5.0f * (dx * dx + dy * dy);                  // coord xy
                float sw = sqrtf(fmaxf(p[2], 1e-6f)) - sqrtf(fmaxf(tw, 1e-6f));
                float sh = sqrtf(fmaxf(p[3], 1e-6f)) - sqrtf(fmaxf(th, 1e-6f));
                acc += 5.0f * (sw * sw + sh * sh);                  // coord wh
                float dc = p[4] - 1.0f;
                acc += dc * dc;                                     // conf obj

                isobj  = true;
                offset = cg * (NB * ROW) + best * ROW + 5;
                lbl    = labels[(size_t)bimg * NBOX + w];
            }
        }
    }

    // ---- class loss: warp-cooperative, batched 4 cells per stall ----
    const int cc0 = lane, cc1 = lane + 32, cc2 = lane + 64;
    const bool has2 = (lane < NC - 64);
    float accb = 0.0f;

    unsigned m = __ballot_sync(FULLMASK, isobj);
    while (__popc(m) >= 4) {
        int l0 = __ffs(m) - 1; m &= m - 1;
        int l1 = __ffs(m) - 1; m &= m - 1;
        int l2 = __ffs(m) - 1; m &= m - 1;
        int l3 = __ffs(m) - 1; m &= m - 1;
        int o0 = __shfl_sync(FULLMASK, offset, l0), b0 = __shfl_sync(FULLMASK, lbl, l0);
        int o1 = __shfl_sync(FULLMASK, offset, l1), b1 = __shfl_sync(FULLMASK, lbl, l1);
        int o2 = __shfl_sync(FULLMASK, offset, l2), b2 = __shfl_sync(FULLMASK, lbl, l2);
        int o3 = __shfl_sync(FULLMASK, offset, l3), b3 = __shfl_sync(FULLMASK, lbl, l3);
        float t00 = __ldcs(pred + o0 + cc0), t01 = __ldcs(pred + o0 + cc1);
        float t10 = __ldcs(pred + o1 + cc0), t11 = __ldcs(pred + o1 + cc1);
        float t20 = __ldcs(pred + o2 + cc0), t21 = __ldcs(pred + o2 + cc1);
        float t30 = __ldcs(pred + o3 + cc0), t31 = __ldcs(pred + o3 + cc1);
        float t02 = has2 ? __ldcs(pred + o0 + cc2) : 0.0f;
        float t12 = has2 ? __ldcs(pred + o1 + cc2) : 0.0f;
        float t22 = has2 ? __ldcs(pred + o2 + cc2) : 0.0f;
        float t32 = has2 ? __ldcs(pred + o3 + cc2) : 0.0f;
        float d;
        d = t00 - (cc0 == b0 ? 1.f : 0.f); acc  += d * d;
        d = t01 - (cc1 == b0 ? 1.f : 0.f); accb += d * d;
        d = t10 - (cc0 == b1 ? 1.f : 0.f); acc  += d * d;
        d = t11 - (cc1 == b1 ? 1.f : 0.f); accb += d * d;
        d = t20 - (cc0 == b2 ? 1.f : 0.f); acc  += d * d;
        d = t21 - (cc1 == b2 ? 1.f : 0.f); accb += d * d;
        d = t30 - (cc0 == b3 ? 1.f : 0.f); acc  += d * d;
        d = t31 - (cc1 == b3 ? 1.f : 0.f); accb += d * d;
        if (has2) {
            d = t02 - (cc2 == b0 ? 1.f : 0.f); acc  += d * d;
            d = t12 - (cc2 == b1 ? 1.f : 0.f); accb += d * d;
            d = t22 - (cc2 == b2 ? 1.f : 0.f); acc  += d * d;
            d = t32 - (cc2 == b3 ? 1.f : 0.f); accb += d * d;
        }
    }
    while (m) {
        int l0 = __ffs(m) - 1; m &= m - 1;
        int o0 = __shfl_sync(FULLMASK, offset, l0), b0 = __shfl_sync(FULLMASK, lbl, l0);
        float t00 = __ldcs(pred + o0 + cc0);
        float t01 = __ldcs(pred + o0 + cc1);
        float t02 = has2 ? __ldcs(pred + o0 + cc2) : 0.0f;
        float d;
        d = t00 - (cc0 == b0 ? 1.f : 0.f); acc  += d * d;
        d = t01 - (cc1 == b0 ? 1.f : 0.f); accb += d * d;
        if (has2) { d = t02 - (cc2 == b0 ? 1.f : 0.f); acc += d * d; }
    }
    acc += accb;

    // ---- block reduce + one atomic ----
    #pragma unroll
    for (int off = 16; off > 0; off >>= 1)
        acc += __shfl_down_sync(FULLMASK, acc, off);
    __shared__ float wsum[NWARPS];
    if (lane == 0) wsum[wib] = acc;
    __syncthreads();
    if (wib == 0) {
        float s = (lane < NWARPS) ? wsum[lane] : 0.0f;
        #pragma unroll
        for (int off = NWARPS / 2; off > 0; off >>= 1)
            s += __shfl_down_sync(FULLMASK, s, off);
        if (lane == 0) atomicAdd(out, s * inv_B);
    }
}

extern "C" void kernel_launch(void* const* d_in, const int* in_sizes, int n_in,
                              void* d_out, int out_size)
{
    const float* pred   = (const float*)d_in[0];
    const float* boxes  = (const float*)d_in[1];
    const int*   labels = (const int*)d_in[2];
    float* out = (float*)d_out;

    const int B = in_sizes[0] / (CELLS * NB * ROW);
    const int total_pairs = B * CELLS * NB;
    const int total_tb    = B * NBOX;
    const float inv_B = 1.0f / (float)B;

    const int gb_pairs = (total_pairs + THREADS - 1) / THREADS;
    const int gb_tb    = (total_tb + THREADS - 1) / THREADS;

    k_encode<<<gb_tb,    THREADS>>>(boxes, out, total_tb);
    k_cell  <<<gb_pairs, THREADS>>>(pred, boxes, labels, out,
                                    total_pairs, inv_B);
}